// round 5
// baseline (speedup 1.0000x reference)
#include <cuda_runtime.h>

#define BB  64
#define TT  4096
#define HH  1024
#define NHH 4

// Scratch: h = x @ W^T + b : [B, T, NH] = 4 MB
__device__ float g_h[BB * TT * NHH];
__device__ float g_part[BB * NHH];

// ---------------------------------------------------------------------------
// Kernel 1: tall-skinny GEMV. One warp computes 8 consecutive (b,t) rows
// (halves smem W traffic per x-byte, doubles per-thread load MLP).
// ---------------------------------------------------------------------------
__global__ __launch_bounds__(256) void k_gemv(const float* __restrict__ x,
                                              const float* __restrict__ W,
                                              const float* __restrict__ bias) {
    __shared__ float4 sW[NHH * (HH / 4)];  // 16 KB
    for (int i = threadIdx.x; i < NHH * (HH / 4); i += 256)
        sW[i] = reinterpret_cast<const float4*>(W)[i];
    __syncthreads();

    const int ROWS = 8;
    int warp_global = (blockIdx.x * 256 + threadIdx.x) >> 5;
    int lane = threadIdx.x & 31;
    long row0 = (long)warp_global * ROWS;

    float acc[ROWS][NHH];
#pragma unroll
    for (int r = 0; r < ROWS; r++)
#pragma unroll
        for (int n = 0; n < NHH; n++) acc[r][n] = 0.0f;

    const float4* xp = reinterpret_cast<const float4*>(x) + row0 * (HH / 4);

#pragma unroll
    for (int k = 0; k < (HH / 4) / 32; k++) {  // 8 iterations
        int idx = lane + k * 32;
        // Front-batch the 8 independent x loads for MLP
        float4 xv[ROWS];
#pragma unroll
        for (int r = 0; r < ROWS; r++)
            xv[r] = xp[(long)r * (HH / 4) + idx];

        float4 w0 = sW[0 * (HH / 4) + idx];
        float4 w1 = sW[1 * (HH / 4) + idx];
        float4 w2 = sW[2 * (HH / 4) + idx];
        float4 w3 = sW[3 * (HH / 4) + idx];
#pragma unroll
        for (int r = 0; r < ROWS; r++) {
            acc[r][0] += xv[r].x * w0.x + xv[r].y * w0.y + xv[r].z * w0.z + xv[r].w * w0.w;
            acc[r][1] += xv[r].x * w1.x + xv[r].y * w1.y + xv[r].z * w1.z + xv[r].w * w1.w;
            acc[r][2] += xv[r].x * w2.x + xv[r].y * w2.y + xv[r].z * w2.z + xv[r].w * w2.w;
            acc[r][3] += xv[r].x * w3.x + xv[r].y * w3.y + xv[r].z * w3.z + xv[r].w * w3.w;
        }
    }

#pragma unroll
    for (int r = 0; r < ROWS; r++)
#pragma unroll
        for (int n = 0; n < NHH; n++)
#pragma unroll
            for (int off = 16; off > 0; off >>= 1)
                acc[r][n] += __shfl_xor_sync(0xffffffffu, acc[r][n], off);

    if (lane == 0) {
        float b0 = bias[0], b1 = bias[1], b2 = bias[2], b3 = bias[3];
#pragma unroll
        for (int r = 0; r < ROWS; r++) {
            float4 o = make_float4(acc[r][0] + b0, acc[r][1] + b1,
                                   acc[r][2] + b2, acc[r][3] + b3);
            reinterpret_cast<float4*>(g_h)[row0 + r] = o;
        }
    }
}

// ---------------------------------------------------------------------------
// Kernel 2: chunked parallel EMA scan + running max. Grid (B, NH), 256 thr.
// ---------------------------------------------------------------------------
__global__ __launch_bounds__(256) void k_scan(const float* __restrict__ decay) {
    const int CH = TT / 256;  // 16
    int b = blockIdx.x, n = blockIdx.y;
    int tid = threadIdx.x;
    int wid = tid >> 5, lane = tid & 31;

    float d = 1.0f / (1.0f + expf(-decay[n]));
    float od = 1.0f - d;

    const float* __restrict__ hp = g_h + (size_t)b * TT * NHH + n;
    int t0 = tid * CH;

    float ema = 0.0f;
#pragma unroll
    for (int i = 0; i < CH; i++)
        ema = d * ema + od * __ldg(&hp[(t0 + i) * NHH]);

    float A = d;
#pragma unroll
    for (int s = 0; s < 4; s++) A = A * A;

    float a = A, bq = ema;
#pragma unroll
    for (int off = 1; off < 32; off <<= 1) {
        float ap = __shfl_up_sync(0xffffffffu, a, off);
        float bp = __shfl_up_sync(0xffffffffu, bq, off);
        if (lane >= off) { bq = a * bp + bq; a = a * ap; }
    }

    __shared__ float sa[8], sb[8], smax[8];
    if (lane == 31) { sa[wid] = a; sb[wid] = bq; }
    __syncthreads();

    float e_w = 0.0f;
#pragma unroll
    for (int w = 0; w < 8; w++)
        if (w < wid) e_w = sa[w] * e_w + sb[w];

    float a_ex = __shfl_up_sync(0xffffffffu, a, 1);
    float b_ex = __shfl_up_sync(0xffffffffu, bq, 1);
    float e_in = (lane == 0) ? e_w : (a_ex * e_w + b_ex);

    ema = e_in;
    float emax = 0.0f;
#pragma unroll
    for (int i = 0; i < CH; i++) {
        ema = d * ema + od * __ldg(&hp[(t0 + i) * NHH]);
        emax = fmaxf(emax, ema);
    }

#pragma unroll
    for (int off = 16; off > 0; off >>= 1)
        emax = fmaxf(emax, __shfl_xor_sync(0xffffffffu, emax, off));
    if (lane == 0) smax[wid] = emax;
    __syncthreads();
    if (tid == 0) {
        float m = smax[0];
#pragma unroll
        for (int w = 1; w < 8; w++) m = fmaxf(m, smax[w]);
        g_part[b * NHH + n] = m;
    }
}

// ---------------------------------------------------------------------------
// Kernel 3: head projection
// ---------------------------------------------------------------------------
__global__ void k_final(const float* __restrict__ head_w,
                        float* __restrict__ out) {
    int b = threadIdx.x;
    if (b < BB) {
        float s = 0.0f;
#pragma unroll
        for (int n = 0; n < NHH; n++)
            s += g_part[b * NHH + n] * head_w[n];
        out[b] = s;
    }
}

// ---------------------------------------------------------------------------
extern "C" void kernel_launch(void* const* d_in, const int* in_sizes, int n_in,
                              void* d_out, int out_size) {
    const float* x      = (const float*)d_in[0];
    const float* W      = (const float*)d_in[1];
    const float* bias   = (const float*)d_in[2];
    const float* decay  = (const float*)d_in[3];
    const float* head_w = (const float*)d_in[4];
    float* out = (float*)d_out;

    // B*T = 262144 rows, 8 rows/warp -> 32768 warps -> 4096 blocks of 8 warps
    int blocks = (BB * TT) / (8 * 8);
    k_gemv<<<blocks, 256>>>(x, W, bias);
    dim3 sg(BB, NHH);
    k_scan<<<sg, 256>>>(decay);
    k_final<<<1, 64>>>(head_w, out);
}